// round 5
// baseline (speedup 1.0000x reference)
#include <cuda_runtime.h>
#include <math.h>

#define B 64
#define S 512
#define H 512
#define IN 84
#define NC 100
#define XW 266
#define HB (H * B)

#define NCTA 128
#define NTH 256

// ---- static device scratch ----
__device__ float g_feats[S * IN * B];              // [S][IN][B]
__device__ float g_hbuf[2 * HB];                   // [2][H][B]
__device__ float g_lstm[(size_t)S * H * B];        // [S][H][B]
__device__ float g_sc[S * B];                      // [S][B] scores -> weights
__device__ float g_ctx[H * B];                     // [H][B]
__device__ unsigned g_ctr;

// ---- SMEM layout (float offsets) ----
#define OFF_H    0                         // h   [512][64]
#define OFF_F    (OFF_H + 512 * 64)        // f   [84][64]
#define OFF_WH   (OFF_F + 84 * 64)         // WhT [512][16]
#define OFF_WI   (OFF_WH + 512 * 16)       // WiT [84][16]
#define OFF_RED  (OFF_WI + 84 * 16)        // red [8][64][18]
#define OFF_BIAS (OFF_RED + 8 * 64 * 18)   // [16]
#define OFF_END  (OFF_BIAS + 16)
#define OFF_MBAR_B (OFF_END * 4)           // byte offset, 8-aligned
#define NMBAR 17                           // 16 h sub-chunks + 1 feats
#define SMEM_BYTES (OFF_MBAR_B + NMBAR * 8)

// ---- packed fp32x2 helpers ----
__device__ __forceinline__ unsigned long long bcast2(float x) {
    unsigned long long r;
    unsigned u = __float_as_uint(x);
    asm("mov.b64 %0, {%1, %1};" : "=l"(r) : "r"(u));
    return r;
}
__device__ __forceinline__ void ffma2(unsigned long long& d,
                                      unsigned long long a,
                                      unsigned long long b) {
    asm("fma.rn.f32x2 %0, %1, %2, %0;" : "+l"(d) : "l"(a), "l"(b));
}
__device__ __forceinline__ float sigf(float x) {
    return __fdividef(1.0f, 1.0f + __expf(-x));
}
__device__ __forceinline__ float tanhfast(float x) {
    return __fdividef(2.0f, 1.0f + __expf(-2.0f * x)) - 1.0f;
}

// ---- mbarrier / bulk-copy helpers ----
__device__ __forceinline__ unsigned smem_u32(const void* p) {
    return (unsigned)__cvta_generic_to_shared(p);
}
__device__ __forceinline__ void mbar_init(unsigned a, unsigned cnt) {
    asm volatile("mbarrier.init.shared.b64 [%0], %1;" :: "r"(a), "r"(cnt) : "memory");
}
__device__ __forceinline__ void mbar_expect(unsigned a, unsigned bytes) {
    asm volatile("mbarrier.arrive.expect_tx.shared.b64 _, [%0], %1;"
                 :: "r"(a), "r"(bytes) : "memory");
}
__device__ __forceinline__ void bulk_g2s(unsigned dst, const void* src,
                                         unsigned bytes, unsigned mbar) {
    asm volatile(
        "cp.async.bulk.shared::cluster.global.mbarrier::complete_tx::bytes "
        "[%0], [%1], %2, [%3];"
        :: "r"(dst), "l"(src), "r"(bytes), "r"(mbar) : "memory");
}
__device__ __forceinline__ void mbar_wait(unsigned a, unsigned parity) {
    asm volatile(
        "{\n\t.reg .pred P;\n\t"
        "W%=:\n\t"
        "mbarrier.try_wait.parity.shared.b64 P, [%0], %1, 0x989680;\n\t"
        "@P bra D%=;\n\t"
        "bra W%=;\n\t"
        "D%=:\n\t}"
        :: "r"(a), "r"(parity) : "memory");
}
__device__ __forceinline__ unsigned elect_one() {
    unsigned pred;
    asm volatile(
        "{\n\t.reg .pred p;\n\t"
        "elect.sync _|p, 0xFFFFFFFF;\n\t"
        "selp.b32 %0, 1, 0, p;\n\t}"
        : "=r"(pred));
    return pred;
}

// ============================================================ reset
__global__ void reset_kernel() {
    int t = blockIdx.x * blockDim.x + threadIdx.x;
    if (t == 0) g_ctr = 0u;
    if (t < HB) g_hbuf[t] = 0.0f;
}

// ============================================================ preprocessing
__global__ void prep_kernel(const float* __restrict__ x) {
    int s = blockIdx.x;
    int b = threadIdx.x;
    const float* xp = x + ((size_t)b * S + s) * XW;
    float cx = xp[0], cy = xp[1];
    #pragma unroll
    for (int hnd = 0; hnd < 2; hnd++) {
        int pbase = (hnd == 0) ? 91 : 112;
        float mnx = 1e30f, mxx = -1e30f, mny = 1e30f, mxy = -1e30f;
        #pragma unroll
        for (int p = 0; p < 21; p++) {
            float px = xp[(pbase + p) * 2];
            float py = xp[(pbase + p) * 2 + 1];
            mnx = fminf(mnx, px); mxx = fmaxf(mxx, px);
            mny = fminf(mny, py); mxy = fmaxf(mxy, py);
        }
        float whx = mxx - mnx, why = mxy - mny;
        bool ok = (whx != 0.0f) && (why != 0.0f);
        float sx = ok ? whx : 1.0f;
        float sy = ok ? why : 1.0f;
        #pragma unroll
        for (int p = 0; p < 21; p++) {
            float px = xp[(pbase + p) * 2];
            float py = xp[(pbase + p) * 2 + 1];
            int i0 = hnd * 42 + p * 2;
            g_feats[((size_t)s * IN + i0) * B + b]     = (px - cx) / sx;
            g_feats[((size_t)s * IN + i0 + 1) * B + b] = (py - cy) / sy;
        }
    }
}

// ============================================================ recurrence
#define STEP_K(hv, wa, wb) do {                                   \
    unsigned long long hb0 = bcast2(hv.x);                        \
    unsigned long long hb1 = bcast2(hv.y);                        \
    unsigned long long hb2 = bcast2(hv.z);                        \
    unsigned long long hb3 = bcast2(hv.w);                        \
    ffma2(acc[0],  wa.x, hb0); ffma2(acc[1],  wa.x, hb1);         \
    ffma2(acc[2],  wa.x, hb2); ffma2(acc[3],  wa.x, hb3);         \
    ffma2(acc[4],  wa.y, hb0); ffma2(acc[5],  wa.y, hb1);         \
    ffma2(acc[6],  wa.y, hb2); ffma2(acc[7],  wa.y, hb3);         \
    ffma2(acc[8],  wb.x, hb0); ffma2(acc[9],  wb.x, hb1);         \
    ffma2(acc[10], wb.x, hb2); ffma2(acc[11], wb.x, hb3);         \
    ffma2(acc[12], wb.y, hb0); ffma2(acc[13], wb.y, hb1);         \
    ffma2(acc[14], wb.y, hb2); ffma2(acc[15], wb.y, hb3);         \
} while (0)

__global__ void __launch_bounds__(NTH, 1)
lstm_kernel(const float* __restrict__ W_ih, const float* __restrict__ W_hh,
            const float* __restrict__ b_ih, const float* __restrict__ b_hh) {
    extern __shared__ float sm[];
    float* h_sm = sm + OFF_H;
    float* f_sm = sm + OFF_F;
    float* Wh_t = sm + OFF_WH;
    float* Wi_t = sm + OFF_WI;
    float* red  = sm + OFF_RED;
    float* bias = sm + OFF_BIAS;

    const int t    = threadIdx.x;
    const int blk  = blockIdx.x;
    const int lane = t & 31;
    const int kp   = t >> 5;       // warp = K chunk of 64
    const int rg   = lane >> 4;    // 0..1
    const int bg   = lane & 15;    // 0..15

    const unsigned smem_base = smem_u32(sm);
    const unsigned mbar0 = smem_base + OFF_MBAR_B;
    const unsigned h_dst = smem_base + OFF_H * 4;
    const unsigned f_dst = smem_base + OFF_F * 4;

    // ---- one-time staging ----
    for (int idx = t; idx < 16 * H; idx += NTH) {
        int r = idx & 15, k = idx >> 4;
        int grow = (r >> 2) * H + blk * 4 + (r & 3);
        Wh_t[k * 16 + r] = W_hh[(size_t)grow * H + k];
    }
    for (int idx = t; idx < 16 * IN; idx += NTH) {
        int r = idx & 15, k = idx >> 4;
        int grow = (r >> 2) * H + blk * 4 + (r & 3);
        Wi_t[k * 16 + r] = W_ih[(size_t)grow * IN + k];
    }
    if (t < 16) {
        int grow = (t >> 2) * H + blk * 4 + (t & 3);
        bias[t] = b_ih[grow] + b_hh[grow];
    }
    if (t == 0) {
        #pragma unroll
        for (int i = 0; i < NMBAR; i++) mbar_init(mbar0 + i * 8, 1);
    }
    __syncthreads();

    // feats K slice for this warp
    const int foff = kp * 10 + (kp < 4 ? kp : 4);
    const int fcnt = (kp < 4) ? 11 : 10;

    // gate-phase mapping
    const int ru = t >> 6;          // unit 0..3
    const int rb = t & 63;          // batch
    const int ubase = blk * 4 + ru;
    float creg = 0.0f;

    const unsigned isleader = elect_one();

    for (int s = 0; s < S; s++) {
        const int cur = s & 1, nxt = cur ^ 1;
        const unsigned par = (unsigned)(s & 1);

        // ---- each warp's leader issues its own 2 sub-chunk copies ----
        if (isleader) {
            asm volatile("fence.proxy.async;" ::: "memory");
            const float* hsrc = g_hbuf + cur * HB + kp * 4096;
            mbar_expect(mbar0 + (2 * kp) * 8, 8192u);
            bulk_g2s(h_dst + kp * 16384u, hsrc, 8192u, mbar0 + (2 * kp) * 8);
            mbar_expect(mbar0 + (2 * kp + 1) * 8, 8192u);
            bulk_g2s(h_dst + kp * 16384u + 8192u, hsrc + 2048, 8192u,
                     mbar0 + (2 * kp + 1) * 8);
            if (kp == 7) {
                mbar_expect(mbar0 + 16 * 8, IN * B * 4u);
                bulk_g2s(f_dst, g_feats + (size_t)s * IN * B, IN * B * 4u,
                         mbar0 + 16 * 8);
            }
        }

        unsigned long long acc[16];
        #pragma unroll
        for (int i = 0; i < 16; i++) acc[i] = 0ull;

        // ---- half 0: k in [kp*64, kp*64+32) ----
        mbar_wait(mbar0 + (2 * kp) * 8, par);
        {
            const int k0 = kp * 64;
            #pragma unroll 8
            for (int k = k0; k < k0 + 32; k++) {
                float4 hv = *(const float4*)(h_sm + k * 64 + bg * 4);
                ulonglong2 wa = *(const ulonglong2*)(Wh_t + k * 16 + rg * 8);
                ulonglong2 wb = *(const ulonglong2*)(Wh_t + k * 16 + rg * 8 + 4);
                STEP_K(hv, wa, wb);
            }
        }
        // ---- half 1 ----
        mbar_wait(mbar0 + (2 * kp + 1) * 8, par);
        {
            const int k0 = kp * 64 + 32;
            #pragma unroll 8
            for (int k = k0; k < k0 + 32; k++) {
                float4 hv = *(const float4*)(h_sm + k * 64 + bg * 4);
                ulonglong2 wa = *(const ulonglong2*)(Wh_t + k * 16 + rg * 8);
                ulonglong2 wb = *(const ulonglong2*)(Wh_t + k * 16 + rg * 8 + 4);
                STEP_K(hv, wa, wb);
            }
        }
        // ---- input projection ----
        mbar_wait(mbar0 + 16 * 8, par);
        {
            #pragma unroll 2
            for (int k = foff; k < foff + fcnt; k++) {
                float4 hv = *(const float4*)(f_sm + k * 64 + bg * 4);
                ulonglong2 wa = *(const ulonglong2*)(Wi_t + k * 16 + rg * 8);
                ulonglong2 wb = *(const ulonglong2*)(Wi_t + k * 16 + rg * 8 + 4);
                STEP_K(hv, wa, wb);
            }
        }

        // ---- write partials: acc[rp*4+j] packs rows (r, r+1) for batch j ----
        // red layout [kp][64 b][18 r-pad]; 64-bit stores of packed pairs
        {
            float* rp0 = red + (kp * 64 + bg * 4) * 18 + rg * 8;
            #pragma unroll
            for (int rp = 0; rp < 4; rp++) {
                #pragma unroll
                for (int j = 0; j < 4; j++) {
                    *(unsigned long long*)(rp0 + j * 18 + rp * 2) = acc[rp * 4 + j];
                }
            }
        }
        __syncthreads();

        // ---- reduce + gates: thread = (unit ru, batch rb) ----
        {
            float g4[4];
            #pragma unroll
            for (int gt = 0; gt < 4; gt++) {
                int r = gt * 4 + ru;
                float v = bias[r];
                #pragma unroll
                for (int p = 0; p < 8; p++)
                    v += red[(p * 64 + rb) * 18 + r];
                g4[gt] = v;
            }
            float i_ = sigf(g4[0]);
            float f_ = sigf(g4[1]);
            float gg = tanhfast(g4[2]);
            float o_ = sigf(g4[3]);
            creg = f_ * creg + i_ * gg;
            float hn = o_ * tanhfast(creg);
            g_hbuf[nxt * HB + ubase * B + rb] = hn;
            g_lstm[((size_t)s * H + ubase) * B + rb] = hn;
        }

        // ---- grid barrier ----
        if (s != S - 1) {
            __syncthreads();
            if (t == 0) {
                __threadfence();
                atomicAdd(&g_ctr, 1u);
                unsigned target = (unsigned)(s + 1) * NCTA;
                unsigned v;
                do {
                    asm volatile("ld.acquire.gpu.u32 %0, [%1];"
                                 : "=r"(v) : "l"(&g_ctr) : "memory");
                } while (v < target);
            }
            __syncthreads();
        }
    }
}

// ============================================================ attention
// scores[s][b] = sum_h attn_w[h] * L[s][h][b]   (one s per CTA)
__global__ void __launch_bounds__(256)
scores_kernel(const float* __restrict__ attn_w) {
    __shared__ float aw[H];
    __shared__ float part[4 * 64];
    int t = threadIdx.x, s = blockIdx.x;
    int st = t >> 6, b = t & 63;
    for (int i = t; i < H; i += 256) aw[i] = attn_w[i];
    __syncthreads();
    const float* Ls = g_lstm + (size_t)s * H * B;
    float acc = 0.0f;
    #pragma unroll 8
    for (int h = st * 128; h < st * 128 + 128; h++)
        acc = fmaf(aw[h], Ls[h * B + b], acc);
    part[st * 64 + b] = acc;
    __syncthreads();
    if (st == 0)
        g_sc[s * B + b] = part[b] + part[64 + b] + part[128 + b] + part[192 + b];
}

__global__ void __launch_bounds__(256)
softmax_kernel(float* __restrict__ out) {
    __shared__ float s_red[8];
    int b = blockIdx.x, t = threadIdx.x;
    int lane = t & 31, warp = t >> 5;
    float v[2];
    v[0] = g_sc[t * B + b];
    v[1] = g_sc[(t + 256) * B + b];
    float m = fmaxf(v[0], v[1]);
    #pragma unroll
    for (int o = 16; o; o >>= 1) m = fmaxf(m, __shfl_xor_sync(~0u, m, o));
    if (lane == 0) s_red[warp] = m;
    __syncthreads();
    m = s_red[0];
    #pragma unroll
    for (int i = 1; i < 8; i++) m = fmaxf(m, s_red[i]);
    __syncthreads();
    float e0 = expf(v[0] - m), e1 = expf(v[1] - m);
    float sum = e0 + e1;
    #pragma unroll
    for (int o = 16; o; o >>= 1) sum += __shfl_xor_sync(~0u, sum, o);
    if (lane == 0) s_red[warp] = sum;
    __syncthreads();
    float tot = 0.0f;
    #pragma unroll
    for (int i = 0; i < 8; i++) tot += s_red[i];
    float inv = 1.0f / tot;
    float w0 = e0 * inv, w1 = e1 * inv;
    g_sc[t * B + b] = w0;
    g_sc[(t + 256) * B + b] = w1;
    out[NC * B + b * S + t] = w0;
    out[NC * B + b * S + t + 256] = w1;
}

// ctx[h][b] = sum_s w[s][b] * L[s][h][b]   (one h per CTA, 4 s-strips)
__global__ void __launch_bounds__(256)
ctx_kernel() {
    __shared__ float part[4 * 64];
    int t = threadIdx.x, h = blockIdx.x;
    int st = t >> 6, b = t & 63;
    float acc = 0.0f;
    const float* Lb = g_lstm + (size_t)h * B + b;
    #pragma unroll 8
    for (int s = st * 128; s < st * 128 + 128; s++)
        acc = fmaf(g_sc[s * B + b], Lb[(size_t)s * H * B], acc);
    part[st * 64 + b] = acc;
    __syncthreads();
    if (st == 0)
        g_ctx[h * B + b] = part[b] + part[64 + b] + part[128 + b] + part[192 + b];
}

__global__ void __launch_bounds__(64)
fc_kernel(const float* __restrict__ fc_w, const float* __restrict__ fc_b,
          float* __restrict__ out) {
    __shared__ float wrow[H];
    int c = blockIdx.x, b = threadIdx.x;
    for (int i = b; i < H; i += 64) wrow[i] = fc_w[(size_t)c * H + i];
    __syncthreads();
    float acc = fc_b[c];
    #pragma unroll 8
    for (int h = 0; h < H; h++)
        acc = fmaf(wrow[h], g_ctx[h * B + b], acc);
    out[b * NC + c] = acc;
}

// ============================================================ launch
extern "C" void kernel_launch(void* const* d_in, const int* in_sizes, int n_in,
                              void* d_out, int out_size) {
    const float* x      = (const float*)d_in[0];
    const float* W_ih   = (const float*)d_in[1];
    const float* W_hh   = (const float*)d_in[2];
    const float* b_ih   = (const float*)d_in[3];
    const float* b_hh   = (const float*)d_in[4];
    const float* attn_w = (const float*)d_in[5];
    const float* fc_w   = (const float*)d_in[6];
    const float* fc_b   = (const float*)d_in[7];
    float* out = (float*)d_out;

    cudaFuncSetAttribute(lstm_kernel,
                         cudaFuncAttributeMaxDynamicSharedMemorySize, SMEM_BYTES);

    reset_kernel<<<(HB + NTH - 1) / NTH, NTH>>>();
    prep_kernel<<<S, B>>>(x);
    lstm_kernel<<<NCTA, NTH, SMEM_BYTES>>>(W_ih, W_hh, b_ih, b_hh);
    scores_kernel<<<S, 256>>>(attn_w);
    softmax_kernel<<<B, 256>>>(out);
    ctx_kernel<<<H, 256>>>();
    fc_kernel<<<NC, 64>>>(fc_w, fc_b, out);
}

// round 6
// speedup vs baseline: 1.0456x; 1.0456x over previous
#include <cuda_runtime.h>
#include <math.h>

#define B 64
#define S 512
#define H 512
#define IN 84
#define NC 100
#define XW 266

#define NGRP 4
#define GCTA 32          // CTAs per group
#define BPG 16           // batches per group
#define UPC 16           // hidden units per CTA
#define ROWS 64          // gate rows per CTA (4 gates x 16 units)
#define NCTA (NGRP * GCTA)
#define NTH 256

// ---- static device scratch ----
__device__ float g_feats[S * NGRP * IN * BPG];       // [S][grp][IN][16]
__device__ float g_hbuf2[2 * NGRP * H * BPG];        // [par][grp][H][16]
__device__ float g_lstm[(size_t)S * H * B];          // [S][H][B]
__device__ float g_sc[S * B];
__device__ float g_ctx[H * B];
__device__ unsigned g_ctrs[64];                      // grp uses [grp*16]

// ---- SMEM layout (float offsets) ----
#define OFF_H    0                            // h    [512][16]   8192
#define OFF_F    (OFF_H + 512 * BPG)          // f    [84][16]    1344
#define OFF_WH   (OFF_F + IN * BPG)           // WhT  [512][64]   32768
#define OFF_WI   (OFF_WH + 512 * ROWS)        // WiT  [84][64]    5376
#define OFF_RED  (OFF_WI + IN * ROWS)         // red  [8][16][66] 8448
#define OFF_BIAS (OFF_RED + 8 * BPG * 66)     // [64]
#define OFF_END  (OFF_BIAS + ROWS)
#define OFF_MBAR_B (OFF_END * 4)
#define NMBAR 17
#define SMEM_BYTES (OFF_MBAR_B + NMBAR * 8)

// ---- packed fp32x2 helpers ----
__device__ __forceinline__ unsigned long long bcast2(float x) {
    unsigned long long r;
    unsigned u = __float_as_uint(x);
    asm("mov.b64 %0, {%1, %1};" : "=l"(r) : "r"(u));
    return r;
}
__device__ __forceinline__ void ffma2(unsigned long long& d,
                                      unsigned long long a,
                                      unsigned long long b) {
    asm("fma.rn.f32x2 %0, %1, %2, %0;" : "+l"(d) : "l"(a), "l"(b));
}
__device__ __forceinline__ float sigf(float x) {
    return __fdividef(1.0f, 1.0f + __expf(-x));
}
__device__ __forceinline__ float tanhfast(float x) {
    return __fdividef(2.0f, 1.0f + __expf(-2.0f * x)) - 1.0f;
}

// ---- mbarrier / bulk-copy helpers ----
__device__ __forceinline__ unsigned smem_u32(const void* p) {
    return (unsigned)__cvta_generic_to_shared(p);
}
__device__ __forceinline__ void mbar_init(unsigned a, unsigned cnt) {
    asm volatile("mbarrier.init.shared.b64 [%0], %1;" :: "r"(a), "r"(cnt) : "memory");
}
__device__ __forceinline__ void mbar_expect(unsigned a, unsigned bytes) {
    asm volatile("mbarrier.arrive.expect_tx.shared.b64 _, [%0], %1;"
                 :: "r"(a), "r"(bytes) : "memory");
}
__device__ __forceinline__ void bulk_g2s(unsigned dst, const void* src,
                                         unsigned bytes, unsigned mbar) {
    asm volatile(
        "cp.async.bulk.shared::cluster.global.mbarrier::complete_tx::bytes "
        "[%0], [%1], %2, [%3];"
        :: "r"(dst), "l"(src), "r"(bytes), "r"(mbar) : "memory");
}
__device__ __forceinline__ void mbar_wait(unsigned a, unsigned parity) {
    asm volatile(
        "{\n\t.reg .pred P;\n\t"
        "W%=:\n\t"
        "mbarrier.try_wait.parity.shared.b64 P, [%0], %1, 0x989680;\n\t"
        "@P bra D%=;\n\t"
        "bra W%=;\n\t"
        "D%=:\n\t}"
        :: "r"(a), "r"(parity) : "memory");
}
__device__ __forceinline__ unsigned elect_one() {
    unsigned pred;
    asm volatile(
        "{\n\t.reg .pred p;\n\t"
        "elect.sync _|p, 0xFFFFFFFF;\n\t"
        "selp.b32 %0, 1, 0, p;\n\t}"
        : "=r"(pred));
    return pred;
}

// ============================================================ reset
__global__ void reset_kernel() {
    int t = blockIdx.x * blockDim.x + threadIdx.x;
    if (t < 64) g_ctrs[t] = 0u;
    if (t < 2 * NGRP * H * BPG) g_hbuf2[t] = 0.0f;
}

// ============================================================ preprocessing
__global__ void prep_kernel(const float* __restrict__ x) {
    int s = blockIdx.x;
    int b = threadIdx.x;
    int grp = b >> 4, bl = b & 15;
    float* fdst = g_feats + ((size_t)s * NGRP + grp) * IN * BPG + bl;
    const float* xp = x + ((size_t)b * S + s) * XW;
    float cx = xp[0], cy = xp[1];
    #pragma unroll
    for (int hnd = 0; hnd < 2; hnd++) {
        int pbase = (hnd == 0) ? 91 : 112;
        float mnx = 1e30f, mxx = -1e30f, mny = 1e30f, mxy = -1e30f;
        #pragma unroll
        for (int p = 0; p < 21; p++) {
            float px = xp[(pbase + p) * 2];
            float py = xp[(pbase + p) * 2 + 1];
            mnx = fminf(mnx, px); mxx = fmaxf(mxx, px);
            mny = fminf(mny, py); mxy = fmaxf(mxy, py);
        }
        float whx = mxx - mnx, why = mxy - mny;
        bool ok = (whx != 0.0f) && (why != 0.0f);
        float sx = ok ? whx : 1.0f;
        float sy = ok ? why : 1.0f;
        #pragma unroll
        for (int p = 0; p < 21; p++) {
            float px = xp[(pbase + p) * 2];
            float py = xp[(pbase + p) * 2 + 1];
            int i0 = hnd * 42 + p * 2;
            fdst[i0 * BPG]       = (px - cx) / sx;
            fdst[(i0 + 1) * BPG] = (py - cy) / sy;
        }
    }
}

// ============================================================ recurrence
// CTA: grp = blk>>5 (16 batches), cg = blk&31 (16 units -> 64 gate rows)
// 8 warps = K chunks of 64. lane: rg = lane>>2 (8 rows), bg = lane&3 (4 b)
#define STEP_K(hv, wa, wb) do {                                   \
    unsigned long long hb0 = bcast2(hv.x);                        \
    unsigned long long hb1 = bcast2(hv.y);                        \
    unsigned long long hb2 = bcast2(hv.z);                        \
    unsigned long long hb3 = bcast2(hv.w);                        \
    ffma2(acc[0],  wa.x, hb0); ffma2(acc[1],  wa.x, hb1);         \
    ffma2(acc[2],  wa.x, hb2); ffma2(acc[3],  wa.x, hb3);         \
    ffma2(acc[4],  wa.y, hb0); ffma2(acc[5],  wa.y, hb1);         \
    ffma2(acc[6],  wa.y, hb2); ffma2(acc[7],  wa.y, hb3);         \
    ffma2(acc[8],  wb.x, hb0); ffma2(acc[9],  wb.x, hb1);         \
    ffma2(acc[10], wb.x, hb2); ffma2(acc[11], wb.x, hb3);         \
    ffma2(acc[12], wb.y, hb0); ffma2(acc[13], wb.y, hb1);         \
    ffma2(acc[14], wb.y, hb2); ffma2(acc[15], wb.y, hb3);         \
} while (0)

__global__ void __launch_bounds__(NTH, 1)
lstm_kernel(const float* __restrict__ W_ih, const float* __restrict__ W_hh,
            const float* __restrict__ b_ih, const float* __restrict__ b_hh) {
    extern __shared__ float sm[];
    float* h_sm = sm + OFF_H;
    float* f_sm = sm + OFF_F;
    float* Wh_t = sm + OFF_WH;
    float* Wi_t = sm + OFF_WI;
    float* red  = sm + OFF_RED;
    float* bias = sm + OFF_BIAS;

    const int t    = threadIdx.x;
    const int blk  = blockIdx.x;
    const int grp  = blk >> 5;
    const int cg   = blk & 31;
    const int lane = t & 31;
    const int kp   = t >> 5;       // warp = K chunk of 64
    const int rg   = lane >> 2;    // 0..7  (8 rows each)
    const int bg   = lane & 3;     // 0..3  (4 batches each)

    const unsigned smem_base = smem_u32(sm);
    const unsigned mbar0 = smem_base + OFF_MBAR_B;
    const unsigned h_dst = smem_base + OFF_H * 4;
    const unsigned f_dst = smem_base + OFF_F * 4;

    // ---- one-time weight staging: WhT[k][64 rows], row = gate*16 + ul ----
    for (int idx = t; idx < ROWS * H; idx += NTH) {
        int r = idx & 63, k = idx >> 6;
        int grow = (r >> 4) * H + cg * UPC + (r & 15);
        Wh_t[k * 64 + r] = W_hh[(size_t)grow * H + k];
    }
    for (int idx = t; idx < ROWS * IN; idx += NTH) {
        int r = idx & 63, k = idx >> 6;
        int grow = (r >> 4) * H + cg * UPC + (r & 15);
        Wi_t[k * 64 + r] = W_ih[(size_t)grow * IN + k];
    }
    if (t < ROWS) {
        int grow = (t >> 4) * H + cg * UPC + (t & 15);
        bias[t] = b_ih[grow] + b_hh[grow];
    }
    if (t == 0) {
        #pragma unroll
        for (int i = 0; i < NMBAR; i++) mbar_init(mbar0 + i * 8, 1);
    }
    __syncthreads();

    // feats K slice for this warp
    const int foff = kp * 10 + (kp < 4 ? kp : 4);
    const int fcnt = (kp < 4) ? 11 : 10;

    // gate-phase mapping: thread = (unit ul, batch b)
    const int ul = t >> 4;          // 0..15
    const int gb = t & 15;          // 0..15
    const int u_glob = cg * UPC + ul;
    float creg = 0.0f;

    const unsigned isleader = elect_one();
    unsigned* my_ctr = &g_ctrs[grp * 16];
    const float* hsrc_grp = g_hbuf2 + (size_t)grp * H * BPG;
    const float* fsrc_grp = g_feats + (size_t)grp * IN * BPG;

    for (int s = 0; s < S; s++) {
        const int cur = s & 1, nxt = cur ^ 1;
        const unsigned par = (unsigned)(s & 1);

        // ---- per-warp leader issues its own copies ----
        if (isleader) {
            asm volatile("fence.proxy.async;" ::: "memory");
            if (kp == 7) {
                mbar_expect(mbar0 + 16 * 8, IN * BPG * 4u);
                bulk_g2s(f_dst, fsrc_grp + (size_t)s * NGRP * IN * BPG,
                         IN * BPG * 4u, mbar0 + 16 * 8);
            }
            const float* hsrc = hsrc_grp + cur * NGRP * H * BPG + kp * 64 * BPG;
            mbar_expect(mbar0 + (2 * kp) * 8, 2048u);
            bulk_g2s(h_dst + kp * 4096u, hsrc, 2048u, mbar0 + (2 * kp) * 8);
            mbar_expect(mbar0 + (2 * kp + 1) * 8, 2048u);
            bulk_g2s(h_dst + kp * 4096u + 2048u, hsrc + 512, 2048u,
                     mbar0 + (2 * kp + 1) * 8);
        }

        unsigned long long acc[16];
        #pragma unroll
        for (int i = 0; i < 16; i++) acc[i] = 0ull;

        // ---- input projection FIRST (feats land fast; h gets headroom) ----
        mbar_wait(mbar0 + 16 * 8, par);
        {
            #pragma unroll 2
            for (int k = foff; k < foff + fcnt; k++) {
                float4 hv = *(const float4*)(f_sm + k * BPG + bg * 4);
                ulonglong2 wa = *(const ulonglong2*)(Wi_t + k * 64 + rg * 8);
                ulonglong2 wb = *(const ulonglong2*)(Wi_t + k * 64 + rg * 8 + 4);
                STEP_K(hv, wa, wb);
            }
        }
        // ---- h-GEMM half 0: k in [kp*64, kp*64+32) ----
        mbar_wait(mbar0 + (2 * kp) * 8, par);
        {
            const int k0 = kp * 64;
            #pragma unroll 8
            for (int k = k0; k < k0 + 32; k++) {
                float4 hv = *(const float4*)(h_sm + k * BPG + bg * 4);
                ulonglong2 wa = *(const ulonglong2*)(Wh_t + k * 64 + rg * 8);
                ulonglong2 wb = *(const ulonglong2*)(Wh_t + k * 64 + rg * 8 + 4);
                STEP_K(hv, wa, wb);
            }
        }
        // ---- half 1 ----
        mbar_wait(mbar0 + (2 * kp + 1) * 8, par);
        {
            const int k0 = kp * 64 + 32;
            #pragma unroll 8
            for (int k = k0; k < k0 + 32; k++) {
                float4 hv = *(const float4*)(h_sm + k * BPG + bg * 4);
                ulonglong2 wa = *(const ulonglong2*)(Wh_t + k * 64 + rg * 8);
                ulonglong2 wb = *(const ulonglong2*)(Wh_t + k * 64 + rg * 8 + 4);
                STEP_K(hv, wa, wb);
            }
        }

        // ---- partials: red[kp][16 b][66 r-pad], u64 row-pair stores ----
        {
            float* rp0 = red + (kp * BPG + bg * 4) * 66 + rg * 8;
            #pragma unroll
            for (int rp = 0; rp < 4; rp++) {
                #pragma unroll
                for (int j = 0; j < 4; j++) {
                    *(unsigned long long*)(rp0 + j * 66 + rp * 2) = acc[rp * 4 + j];
                }
            }
        }
        __syncthreads();

        // ---- reduce + gates: thread = (unit ul, batch gb) ----
        {
            float g4[4];
            #pragma unroll
            for (int gt = 0; gt < 4; gt++) {
                int r = gt * UPC + ul;
                float v = bias[r];
                #pragma unroll
                for (int p = 0; p < 8; p++)
                    v += red[(p * BPG + gb) * 66 + r];
                g4[gt] = v;
            }
            float i_ = sigf(g4[0]);
            float f_ = sigf(g4[1]);
            float gg = tanhfast(g4[2]);
            float o_ = sigf(g4[3]);
            creg = f_ * creg + i_ * gg;
            float hn = o_ * tanhfast(creg);
            g_hbuf2[(size_t)(nxt * NGRP + grp) * H * BPG + u_glob * BPG + gb] = hn;
            g_lstm[((size_t)s * H + u_glob) * B + grp * BPG + gb] = hn;
        }

        // ---- group barrier (32 CTAs, own counter) ----
        if (s != S - 1) {
            __syncthreads();
            if (t == 0) {
                __threadfence();
                atomicAdd(my_ctr, 1u);
                unsigned target = (unsigned)(s + 1) * GCTA;
                unsigned v;
                do {
                    asm volatile("ld.acquire.gpu.u32 %0, [%1];"
                                 : "=r"(v) : "l"(my_ctr) : "memory");
                } while (v < target);
            }
            __syncthreads();
        }
    }
}

// ============================================================ attention
__global__ void __launch_bounds__(256)
scores_kernel(const float* __restrict__ attn_w) {
    __shared__ float aw[H];
    __shared__ float part[4 * 64];
    int t = threadIdx.x, s = blockIdx.x;
    int st = t >> 6, b = t & 63;
    for (int i = t; i < H; i += 256) aw[i] = attn_w[i];
    __syncthreads();
    const float* Ls = g_lstm + (size_t)s * H * B;
    float acc = 0.0f;
    #pragma unroll 8
    for (int h = st * 128; h < st * 128 + 128; h++)
        acc = fmaf(aw[h], Ls[h * B + b], acc);
    part[st * 64 + b] = acc;
    __syncthreads();
    if (st == 0)
        g_sc[s * B + b] = part[b] + part[64 + b] + part[128 + b] + part[192 + b];
}

__global__ void __launch_bounds__(256)
softmax_kernel(float* __restrict__ out) {
    __shared__ float s_red[8];
    int b = blockIdx.x, t = threadIdx.x;
    int lane = t & 31, warp = t >> 5;
    float v[2];
    v[0] = g_sc[t * B + b];
    v[1] = g_sc[(t + 256) * B + b];
    float m = fmaxf(v[0], v[1]);
    #pragma unroll
    for (int o = 16; o; o >>= 1) m = fmaxf(m, __shfl_xor_sync(~0u, m, o));
    if (lane == 0) s_red[warp] = m;
    __syncthreads();
    m = s_red[0];
    #pragma unroll
    for (int i = 1; i < 8; i++) m = fmaxf(m, s_red[i]);
    __syncthreads();
    float e0 = expf(v[0] - m), e1 = expf(v[1] - m);
    float sum = e0 + e1;
    #pragma unroll
    for (int o = 16; o; o >>= 1) sum += __shfl_xor_sync(~0u, sum, o);
    if (lane == 0) s_red[warp] = sum;
    __syncthreads();
    float tot = 0.0f;
    #pragma unroll
    for (int i = 0; i < 8; i++) tot += s_red[i];
    float inv = 1.0f / tot;
    float w0 = e0 * inv, w1 = e1 * inv;
    g_sc[t * B + b] = w0;
    g_sc[(t + 256) * B + b] = w1;
    out[NC * B + b * S + t] = w0;
    out[NC * B + b * S + t + 256] = w1;
}

__global__ void __launch_bounds__(256)
ctx_kernel() {
    __shared__ float part[4 * 64];
    int t = threadIdx.x, h = blockIdx.x;
    int st = t >> 6, b = t & 63;
    float acc = 0.0f;
    const float* Lb = g_lstm + (size_t)h * B + b;
    #pragma unroll 8
    for (int s = st * 128; s < st * 128 + 128; s++)
        acc = fmaf(g_sc[s * B + b], Lb[(size_t)s * H * B], acc);
    part[st * 64 + b] = acc;
    __syncthreads();
    if (st == 0)
        g_ctx[h * B + b] = part[b] + part[64 + b] + part[128 + b] + part[192 + b];
}

__global__ void __launch_bounds__(64)
fc_kernel(const float* __restrict__ fc_w, const float* __restrict__ fc_b,
          float* __restrict__ out) {
    __shared__ float wrow[H];
    int c = blockIdx.x, b = threadIdx.x;
    for (int i = b; i < H; i += 64) wrow[i] = fc_w[(size_t)c * H + i];
    __syncthreads();
    float acc = fc_b[c];
    #pragma unroll 8
    for (int h = 0; h < H; h++)
        acc = fmaf(wrow[h], g_ctx[h * B + b], acc);
    out[b * NC + c] = acc;
}

// ============================================================ launch
extern "C" void kernel_launch(void* const* d_in, const int* in_sizes, int n_in,
                              void* d_out, int out_size) {
    const float* x      = (const float*)d_in[0];
    const float* W_ih   = (const float*)d_in[1];
    const float* W_hh   = (const float*)d_in[2];
    const float* b_ih   = (const float*)d_in[3];
    const float* b_hh   = (const float*)d_in[4];
    const float* attn_w = (const float*)d_in[5];
    const float* fc_w   = (const float*)d_in[6];
    const float* fc_b   = (const float*)d_in[7];
    float* out = (float*)d_out;

    cudaFuncSetAttribute(lstm_kernel,
                         cudaFuncAttributeMaxDynamicSharedMemorySize, SMEM_BYTES);

    reset_kernel<<<(2 * NGRP * H * BPG + NTH - 1) / NTH, NTH>>>();
    prep_kernel<<<S, B>>>(x);
    lstm_kernel<<<NCTA, NTH, SMEM_BYTES>>>(W_ih, W_hh, b_ih, b_hh);
    scores_kernel<<<S, 256>>>(attn_w);
    softmax_kernel<<<B, 256>>>(out);
    ctx_kernel<<<H, 256>>>();
    fc_kernel<<<NC, 64>>>(fc_w, fc_b, out);
}